// round 3
// baseline (speedup 1.0000x reference)
#include <cuda_runtime.h>
#include <cuda_bf16.h>
#include <math.h>

// ---------------------------------------------------------------------------
// MoE FFN: N=8192 tokens, D=1024, H=4096, E=8 experts, top-2 gating.
// Pipeline: router -> scan -> build permutation -> GEMM1(+GELU) -> GEMM2 ->
//           gated combine.  GEMMs use mma.sync tf32 (RNA-rounded inputs).
// ---------------------------------------------------------------------------

#define NTOK   8192
#define DDIM   1024
#define HDIM   4096
#define NEXP   8
#define NASSIGN (NTOK * 2)

// scratch (no runtime allocation allowed)
__device__ int   g_counts[NEXP];
__device__ int   g_offsets[NEXP];
__device__ int   g_cursor[NEXP];
__device__ int   g_tok_e[NTOK * 2];
__device__ float g_tok_g[NTOK * 2];
__device__ int   g_tok_pos[NTOK * 2];
__device__ int   g_perm[NASSIGN];
__device__ __align__(128) float g_h[(size_t)NASSIGN * HDIM];   // 256 MB
__device__ __align__(128) float g_y[(size_t)NASSIGN * DDIM];   // 64 MB

__device__ __forceinline__ float to_tf32(float x) {
    unsigned r;
    asm("cvt.rna.tf32.f32 %0, %1;" : "=r"(r) : "f"(x));
    return __uint_as_float(r);
}

__device__ __forceinline__ float gelu_tanh(float x) {
    const float k0 = 0.7978845608028654f;   // sqrt(2/pi)
    const float k1 = 0.044715f;
    float x3 = x * x * x;
    return 0.5f * x * (1.0f + tanhf(k0 * (x + k1 * x3)));
}

__device__ __forceinline__ void mma_tf32(float c[4],
                                         unsigned a0, unsigned a1, unsigned a2, unsigned a3,
                                         unsigned b0, unsigned b1) {
    asm volatile(
        "mma.sync.aligned.m16n8k8.row.col.f32.tf32.tf32.f32 "
        "{%0,%1,%2,%3}, {%4,%5,%6,%7}, {%8,%9}, {%0,%1,%2,%3};\n"
        : "+f"(c[0]), "+f"(c[1]), "+f"(c[2]), "+f"(c[3])
        : "r"(a0), "r"(a1), "r"(a2), "r"(a3), "r"(b0), "r"(b1));
}

// ---------------------------------------------------------------------------
// init: zero per-expert counters
// ---------------------------------------------------------------------------
__global__ void init_kernel() {
    if (threadIdx.x < NEXP) g_counts[threadIdx.x] = 0;
}

// ---------------------------------------------------------------------------
// router: logits = x @ router_w + b ; top-2 ; softmax over the 2 picked logits
// one warp per token, 8 tokens per block; router_w staged in SMEM
// ---------------------------------------------------------------------------
__global__ __launch_bounds__(256) void router_kernel(
    const float* __restrict__ x,
    const float* __restrict__ rw,
    const float* __restrict__ rb)
{
    __shared__ float s_rw[DDIM * NEXP];   // 32 KB
    for (int i = threadIdx.x; i < DDIM * NEXP; i += 256) s_rw[i] = rw[i];
    __syncthreads();

    int warp = threadIdx.x >> 5;
    int lane = threadIdx.x & 31;
    int tok  = blockIdx.x * 8 + warp;
    const float* xr = x + (size_t)tok * DDIM;

    float acc[NEXP];
#pragma unroll
    for (int e = 0; e < NEXP; e++) acc[e] = 0.0f;

    for (int i = lane; i < DDIM; i += 32) {
        float xv = xr[i];
        const float* r = s_rw + i * NEXP;
#pragma unroll
        for (int e = 0; e < NEXP; e++) acc[e] += xv * r[e];
    }
#pragma unroll
    for (int off = 16; off > 0; off >>= 1) {
#pragma unroll
        for (int e = 0; e < NEXP; e++)
            acc[e] += __shfl_xor_sync(0xFFFFFFFFu, acc[e], off);
    }

    if (lane == 0) {
        float lg[NEXP];
#pragma unroll
        for (int e = 0; e < NEXP; e++) lg[e] = acc[e] + rb[e];
        // top-2 (earliest index wins ties, matching top_k)
        int i0 = 0;
#pragma unroll
        for (int e = 1; e < NEXP; e++) if (lg[e] > lg[i0]) i0 = e;
        int i1 = -1;
#pragma unroll
        for (int e = 0; e < NEXP; e++) {
            if (e == i0) continue;
            if (i1 < 0 || lg[e] > lg[i1]) i1 = e;
        }
        float d  = lg[i1] - lg[i0];         // <= 0
        float g0 = 1.0f / (1.0f + expf(d));
        float g1 = 1.0f - g0;

        g_tok_e[2 * tok]     = i0;
        g_tok_e[2 * tok + 1] = i1;
        g_tok_g[2 * tok]     = g0;
        g_tok_g[2 * tok + 1] = g1;
        atomicAdd(&g_counts[i0], 1);
        atomicAdd(&g_counts[i1], 1);
    }
}

// ---------------------------------------------------------------------------
// scan: exclusive prefix over 8 expert counts
// ---------------------------------------------------------------------------
__global__ void scan_kernel() {
    if (threadIdx.x == 0) {
        int s = 0;
        for (int e = 0; e < NEXP; e++) {
            g_offsets[e] = s;
            g_cursor[e]  = s;
            s += g_counts[e];
        }
    }
}

// ---------------------------------------------------------------------------
// build: scatter tokens into per-expert contiguous slots
// ---------------------------------------------------------------------------
__global__ void build_kernel() {
    int tok = blockIdx.x * blockDim.x + threadIdx.x;
    if (tok >= NTOK) return;
#pragma unroll
    for (int k = 0; k < 2; k++) {
        int e   = g_tok_e[2 * tok + k];
        int pos = atomicAdd(&g_cursor[e], 1);
        g_perm[pos]          = tok;
        g_tok_pos[2 * tok + k] = pos;
    }
}

// ---------------------------------------------------------------------------
// grouped GEMM: C[cnt,N] = A[cnt,K] @ W[e][K,N]  (tf32 mma, fp32 accum)
// PHASE1: A = gathered x rows (via g_perm), epilogue = gelu(v + b1), C = g_h
// PHASE2: A = g_h rows (compacted),          epilogue = identity,      C = g_y
// block tile 128x128x16, 256 threads, double-buffered SMEM
// ---------------------------------------------------------------------------
#define BM 128
#define BN 128
#define BK 16

template<int KDIM, int NDIM, bool PHASE1>
__global__ __launch_bounds__(256) void gemm_kernel(
    const float* __restrict__ Ain,
    const float* __restrict__ Wbase,
    const float* __restrict__ biasBase)
{
    int e   = blockIdx.z;
    int cnt = g_counts[e];
    int m0  = blockIdx.y * BM;
    if (m0 >= cnt) return;
    int off = g_offsets[e];
    int n0  = blockIdx.x * BN;

    const float* W  = Wbase + (size_t)e * KDIM * NDIM;
    const float* A  = PHASE1 ? Ain : g_h;
    float*       Cp = PHASE1 ? g_h : g_y;

    __shared__ float As[2][BM][20];    // pad 16->20: conflict-free frag loads
    __shared__ float Bs[2][BK][136];   // pad 128->136

    int t    = threadIdx.x;
    int lane = t & 31;
    int warp = t >> 5;
    int wr   = warp >> 2;   // 0..1 -> 64 rows each
    int wc   = warp & 3;    // 0..3 -> 32 cols each
    int gid  = lane >> 2;   // 0..7
    int t4   = lane & 3;    // 0..3

    // per-thread A sources (2 float4 per stage)
    const float* aP[2];
    int aRow[2], aCol[2];
#pragma unroll
    for (int i = 0; i < 2; i++) {
        int idx  = t + i * 256;
        int r    = idx >> 2;          // 0..127
        int c4   = (idx & 3) << 2;    // 0,4,8,12
        int grow = m0 + r;
        int src;
        if (PHASE1) src = g_perm[off + ((grow < cnt) ? grow : 0)];
        else        src = off + ((grow < cnt) ? grow : 0);
        aP[i]   = A + (size_t)src * KDIM + c4;
        aRow[i] = r;
        aCol[i] = c4;
    }
    // per-thread B sources (2 float4 per stage)
    const float* bP[2];
    int bRow[2], bCol[2];
#pragma unroll
    for (int i = 0; i < 2; i++) {
        int idx = t + i * 256;
        int br  = idx >> 5;           // 0..15
        int bc  = (idx & 31) << 2;    // 0..124
        bP[i]   = W + (size_t)br * NDIM + n0 + bc;
        bRow[i] = br;
        bCol[i] = bc;
    }

    float4 aReg[2], bReg[2];
#pragma unroll
    for (int i = 0; i < 2; i++) {
        aReg[i] = *(const float4*)(aP[i]);
        bReg[i] = *(const float4*)(bP[i]);
    }
    // stage 0
#pragma unroll
    for (int i = 0; i < 2; i++) {
        As[0][aRow[i]][aCol[i] + 0] = to_tf32(aReg[i].x);
        As[0][aRow[i]][aCol[i] + 1] = to_tf32(aReg[i].y);
        As[0][aRow[i]][aCol[i] + 2] = to_tf32(aReg[i].z);
        As[0][aRow[i]][aCol[i] + 3] = to_tf32(aReg[i].w);
        Bs[0][bRow[i]][bCol[i] + 0] = to_tf32(bReg[i].x);
        Bs[0][bRow[i]][bCol[i] + 1] = to_tf32(bReg[i].y);
        Bs[0][bRow[i]][bCol[i] + 2] = to_tf32(bReg[i].z);
        Bs[0][bRow[i]][bCol[i] + 3] = to_tf32(bReg[i].w);
    }
    __syncthreads();

    float acc[4][4][4] = {};

    const int KT = KDIM / BK;
    int buf = 0;
    for (int kt = 0; kt < KT; ++kt) {
        if (kt + 1 < KT) {
            size_t ao = (size_t)(kt + 1) * BK;
            size_t bo = (size_t)(kt + 1) * BK * NDIM;
#pragma unroll
            for (int i = 0; i < 2; i++) {
                aReg[i] = *(const float4*)(aP[i] + ao);
                bReg[i] = *(const float4*)(bP[i] + bo);
            }
        }
#pragma unroll
        for (int ks = 0; ks < 2; ++ks) {
            int kk = ks * 8;
            unsigned af[4][4];
#pragma unroll
            for (int mt = 0; mt < 4; mt++) {
                int r = wr * 64 + mt * 16;
                af[mt][0] = __float_as_uint(As[buf][r + gid    ][kk + t4    ]);
                af[mt][1] = __float_as_uint(As[buf][r + gid + 8][kk + t4    ]);
                af[mt][2] = __float_as_uint(As[buf][r + gid    ][kk + t4 + 4]);
                af[mt][3] = __float_as_uint(As[buf][r + gid + 8][kk + t4 + 4]);
            }
            unsigned bf[4][2];
#pragma unroll
            for (int nt = 0; nt < 4; nt++) {
                int cc = wc * 32 + nt * 8 + gid;
                bf[nt][0] = __float_as_uint(Bs[buf][kk + t4    ][cc]);
                bf[nt][1] = __float_as_uint(Bs[buf][kk + t4 + 4][cc]);
            }
#pragma unroll
            for (int mt = 0; mt < 4; mt++)
#pragma unroll
                for (int nt = 0; nt < 4; nt++)
                    mma_tf32(acc[mt][nt], af[mt][0], af[mt][1], af[mt][2], af[mt][3],
                             bf[nt][0], bf[nt][1]);
        }
        if (kt + 1 < KT) {
            int nb = buf ^ 1;
#pragma unroll
            for (int i = 0; i < 2; i++) {
                As[nb][aRow[i]][aCol[i] + 0] = to_tf32(aReg[i].x);
                As[nb][aRow[i]][aCol[i] + 1] = to_tf32(aReg[i].y);
                As[nb][aRow[i]][aCol[i] + 2] = to_tf32(aReg[i].z);
                As[nb][aRow[i]][aCol[i] + 3] = to_tf32(aReg[i].w);
                Bs[nb][bRow[i]][bCol[i] + 0] = to_tf32(bReg[i].x);
                Bs[nb][bRow[i]][bCol[i] + 1] = to_tf32(bReg[i].y);
                Bs[nb][bRow[i]][bCol[i] + 2] = to_tf32(bReg[i].z);
                Bs[nb][bRow[i]][bCol[i] + 3] = to_tf32(bReg[i].w);
            }
        }
        __syncthreads();
        buf ^= 1;
    }

    // epilogue
    const float* bias = PHASE1 ? (biasBase + (size_t)e * NDIM) : nullptr;
#pragma unroll
    for (int mt = 0; mt < 4; mt++) {
#pragma unroll
        for (int nt = 0; nt < 4; nt++) {
            int rloc0 = wr * 64 + mt * 16 + gid;
            int col0  = n0 + wc * 32 + nt * 8 + t4 * 2;
#pragma unroll
            for (int q = 0; q < 4; q++) {
                int rloc = rloc0 + ((q >= 2) ? 8 : 0);
                int col  = col0 + (q & 1);
                int grow = m0 + rloc;
                if (grow < cnt) {
                    float v = acc[mt][nt][q];
                    if (PHASE1) v = gelu_tanh(v + bias[col]);
                    Cp[(size_t)(off + grow) * NDIM + col] = v;
                }
            }
        }
    }
}

// ---------------------------------------------------------------------------
// combine: out[t] = g0*(y[p0]+b2[e0]) + g1*(y[p1]+b2[e1])
// one block per token, 256 threads * float4 = 1024 cols
// ---------------------------------------------------------------------------
__global__ __launch_bounds__(256) void combine_kernel(
    const float* __restrict__ b2,
    float* __restrict__ out)
{
    int tok = blockIdx.x;
    int e0  = g_tok_e[2 * tok];
    int e1  = g_tok_e[2 * tok + 1];
    float gg0 = g_tok_g[2 * tok];
    float gg1 = g_tok_g[2 * tok + 1];
    int p0  = g_tok_pos[2 * tok];
    int p1  = g_tok_pos[2 * tok + 1];

    int j = threadIdx.x * 4;
    float4 y0  = *(const float4*)(g_y + (size_t)p0 * DDIM + j);
    float4 y1  = *(const float4*)(g_y + (size_t)p1 * DDIM + j);
    float4 bb0 = *(const float4*)(b2 + (size_t)e0 * DDIM + j);
    float4 bb1 = *(const float4*)(b2 + (size_t)e1 * DDIM + j);
    float4 o;
    o.x = gg0 * (y0.x + bb0.x) + gg1 * (y1.x + bb1.x);
    o.y = gg0 * (y0.y + bb0.y) + gg1 * (y1.y + bb1.y);
    o.z = gg0 * (y0.z + bb0.z) + gg1 * (y1.z + bb1.z);
    o.w = gg0 * (y0.w + bb0.w) + gg1 * (y1.w + bb1.w);
    *(float4*)(out + (size_t)tok * DDIM + j) = o;
}

// ---------------------------------------------------------------------------
extern "C" void kernel_launch(void* const* d_in, const int* in_sizes, int n_in,
                              void* d_out, int out_size) {
    const float* x   = (const float*)d_in[0];
    const float* rw  = (const float*)d_in[1];
    const float* rb  = (const float*)d_in[2];
    const float* w1  = (const float*)d_in[3];
    const float* b1  = (const float*)d_in[4];
    const float* w2  = (const float*)d_in[5];
    const float* b2  = (const float*)d_in[6];
    float* out = (float*)d_out;

    init_kernel<<<1, 32>>>();
    router_kernel<<<NTOK / 8, 256>>>(x, rw, rb);
    scan_kernel<<<1, 32>>>();
    build_kernel<<<(NTOK + 255) / 256, 256>>>();

    // GEMM1: [cnt,1024] @ [1024,4096] -> gelu -> g_h
    gemm_kernel<DDIM, HDIM, true><<<dim3(HDIM / BN, NTOK / BM, NEXP), 256>>>(x, w1, b1);
    // GEMM2: [cnt,4096] @ [4096,1024] -> g_y
    gemm_kernel<HDIM, DDIM, false><<<dim3(DDIM / BN, NTOK / BM, NEXP), 256>>>(x, w2, b1);

    combine_kernel<<<NTOK, 256>>>(b2, out);
}

// round 10
// speedup vs baseline: 1.5116x; 1.5116x over previous
#include <cuda_runtime.h>
#include <cuda_fp16.h>
#include <cstdint>
#include <math.h>

// ---------------------------------------------------------------------------
// MoE FFN: N=8192, D=1024, H=4096, E=8, top-2.
// router -> scan -> build -> HMMA fp16 grouped GEMM1(+GELU) -> GEMM2 ->
// gated combine.  Structure cloned from the round-3 kernel that PASSED the
// harness memory checks: static __shared__, double buffering, plain global
// loads, inline-asm mma only.  Delta vs R3: fp16 m16n8k16 instead of tf32
// m16n8k8, half2-packed smem tiles, fp16 g_h, approx-tanh GELU, and no prep
// kernels (conversion fused into the tile loaders).
// ---------------------------------------------------------------------------

#define NTOK   8192
#define DDIM   1024
#define HDIM   4096
#define NEXP   8
#define NASSIGN (NTOK * 2)

// ------------------------- device scratch ----------------------------------
__device__ int   g_counts[NEXP];
__device__ int   g_offsets[NEXP];
__device__ int   g_cursor[NEXP];
__device__ int   g_tok_e[NASSIGN];
__device__ float g_tok_g[NASSIGN];
__device__ int   g_tok_pos[NASSIGN];
__device__ int   g_perm[NASSIGN];
__device__ __align__(128) __half g_h[(size_t)NASSIGN * HDIM];   // 128 MB
__device__ __align__(128) float  g_y[(size_t)NASSIGN * DDIM];   // 64 MB

// ------------------------- helpers -----------------------------------------
__device__ __forceinline__ float gelu_fast(float x) {
    float u = 0.7978845608028654f * x * (1.0f + 0.044715f * x * x);
    float t;
    asm("tanh.approx.f32 %0, %1;" : "=f"(t) : "f"(u));
    return 0.5f * x * (1.0f + t);
}

__device__ __forceinline__ unsigned pack_h2(float lo, float hi) {
    // u32 with low 16 bits = half(lo), high 16 = half(hi); intrinsics only
    unsigned ulo = (unsigned)__half_as_ushort(__float2half_rn(lo));
    unsigned uhi = (unsigned)__half_as_ushort(__float2half_rn(hi));
    return ulo | (uhi << 16);
}

#define MMA_F16(c, a0, a1, a2, a3, b0, b1) \
    asm volatile( \
        "mma.sync.aligned.m16n8k16.row.col.f32.f16.f16.f32 " \
        "{%0,%1,%2,%3}, {%4,%5,%6,%7}, {%8,%9}, {%0,%1,%2,%3};\n" \
        : "+f"((c)[0]), "+f"((c)[1]), "+f"((c)[2]), "+f"((c)[3]) \
        : "r"(a0), "r"(a1), "r"(a2), "r"(a3), "r"(b0), "r"(b1))

// ------------------------- small kernels (verbatim from R3) ----------------
__global__ void init_kernel() {
    if (threadIdx.x < NEXP) g_counts[threadIdx.x] = 0;
}

__global__ __launch_bounds__(256) void router_kernel(
    const float* __restrict__ x, const float* __restrict__ rw, const float* __restrict__ rb)
{
    __shared__ float s_rw[DDIM * NEXP];
    for (int i = threadIdx.x; i < DDIM * NEXP; i += 256) s_rw[i] = rw[i];
    __syncthreads();
    int warp = threadIdx.x >> 5, lane = threadIdx.x & 31;
    int tok  = blockIdx.x * 8 + warp;
    const float* xr = x + (size_t)tok * DDIM;
    float acc[NEXP];
#pragma unroll
    for (int e = 0; e < NEXP; e++) acc[e] = 0.0f;
    for (int i = lane; i < DDIM; i += 32) {
        float xv = xr[i];
        const float* r = s_rw + i * NEXP;
#pragma unroll
        for (int e = 0; e < NEXP; e++) acc[e] += xv * r[e];
    }
#pragma unroll
    for (int off = 16; off > 0; off >>= 1)
#pragma unroll
        for (int e = 0; e < NEXP; e++)
            acc[e] += __shfl_xor_sync(0xFFFFFFFFu, acc[e], off);
    if (lane == 0) {
        float lg[NEXP];
#pragma unroll
        for (int e = 0; e < NEXP; e++) lg[e] = acc[e] + rb[e];
        int i0 = 0;
#pragma unroll
        for (int e = 1; e < NEXP; e++) if (lg[e] > lg[i0]) i0 = e;
        int i1 = -1;
#pragma unroll
        for (int e = 0; e < NEXP; e++) {
            if (e == i0) continue;
            if (i1 < 0 || lg[e] > lg[i1]) i1 = e;
        }
        float d  = lg[i1] - lg[i0];
        float g0 = 1.0f / (1.0f + expf(d));
        g_tok_e[2 * tok] = i0;  g_tok_e[2 * tok + 1] = i1;
        g_tok_g[2 * tok] = g0;  g_tok_g[2 * tok + 1] = 1.0f - g0;
        atomicAdd(&g_counts[i0], 1);
        atomicAdd(&g_counts[i1], 1);
    }
}

__global__ void scan_kernel() {
    if (threadIdx.x == 0) {
        int s = 0;
        for (int e = 0; e < NEXP; e++) { g_offsets[e] = s; g_cursor[e] = s; s += g_counts[e]; }
    }
}

__global__ void build_kernel() {
    int tok = blockIdx.x * blockDim.x + threadIdx.x;
    if (tok >= NTOK) return;
#pragma unroll
    for (int k = 0; k < 2; k++) {
        int e = g_tok_e[2 * tok + k];
        int pos = atomicAdd(&g_cursor[e], 1);
        g_perm[pos] = tok;
        g_tok_pos[2 * tok + k] = pos;
    }
}

// ------------------------- fp16 HMMA grouped GEMM --------------------------
// C[cnt,NDIM] = A[cnt,KDIM] @ W[e][KDIM,NDIM]   (W in natural [K][N] layout)
// block tile 128x128x16, 256 threads (8 warps, warp tile 64x32), double buffer
// smem: sA[m][k2] half2-packed (PA=12 -> conflict-free A frags)
//       sB[k2][n] half2-packed along k (PB=136 -> conflict-free B frags)
#define BM 128
#define BN 128
#define BK 16
#define PA 12
#define PB 136

template<int KDIM, bool PHASE1>
__global__ __launch_bounds__(256) void gemm_hmma(
    const float* __restrict__ Ain,      // PHASE1: x (fp32); PHASE2 unused
    const float* __restrict__ Wbase,    // w1 / w2 (fp32, [E][K][N])
    const float* __restrict__ biasBase) // b1 (PHASE1 only)
{
    const int NDIM = PHASE1 ? HDIM : DDIM;
    int e = blockIdx.z;
    int cnt = g_counts[e];
    int m0 = blockIdx.y * BM;
    if (m0 >= cnt) return;
    int off = g_offsets[e];
    int n0 = blockIdx.x * BN;

    const float* W = Wbase + (size_t)e * KDIM * NDIM;

    __shared__ __align__(16) __half2 sA[2][BM][PA];       // [m][k2]; 12288 B
    __shared__ __align__(16) __half2 sB[2][BK / 2][PB];   // [k2][n]; 8704 B

    int t = threadIdx.x, lane = t & 31, warp = t >> 5;
    int wr = warp >> 2, wc = warp & 3;       // warp tile: rows wr*64, cols wc*32
    int gid = lane >> 2, t4 = lane & 3;

    // ---- A loader: 2 chunks/thread; chunk = (row, 4 consecutive k) --------
    int aR0 = t >> 2,          aC0 = (t & 3) << 2;
    int aR1 = (t + 256) >> 2,  aC1 = ((t + 256) & 3) << 2;
    size_t aOfs0, aOfs1;
    {
        int gr0 = m0 + aR0; if (gr0 >= cnt) gr0 = cnt - 1;
        int gr1 = m0 + aR1; if (gr1 >= cnt) gr1 = cnt - 1;
        int s0 = PHASE1 ? g_perm[off + gr0] : (off + gr0);
        int s1 = PHASE1 ? g_perm[off + gr1] : (off + gr1);
        aOfs0 = (size_t)s0 * KDIM + aC0;
        aOfs1 = (size_t)s1 * KDIM + aC1;
    }
    // ---- B loader: 1 cell/thread = rows {2kp,2kp+1} x 4 consecutive n -----
    int kp  = t >> 5;                  // 0..7
    int bn4 = lane << 2;               // 0..124
    size_t bOfs = (size_t)(2 * kp) * NDIM + n0 + bn4;

    const int KT = KDIM / BK;

    // ---- prefetch registers ----
    float4 av0, av1, bv0, bv1;
    uint2  ah0, ah1;
    if (PHASE1) {
        av0 = *(const float4*)(Ain + aOfs0);
        av1 = *(const float4*)(Ain + aOfs1);
    } else {
        ah0 = *(const uint2*)(g_h + aOfs0);
        ah1 = *(const uint2*)(g_h + aOfs1);
    }
    bv0 = *(const float4*)(W + bOfs);
    bv1 = *(const float4*)(W + bOfs + NDIM);

    // ---- store stage 0 ----
    {
        if (PHASE1) {
            uint2 pa0 = make_uint2(pack_h2(av0.x, av0.y), pack_h2(av0.z, av0.w));
            uint2 pa1 = make_uint2(pack_h2(av1.x, av1.y), pack_h2(av1.z, av1.w));
            *(uint2*)&sA[0][aR0][aC0 >> 1] = pa0;
            *(uint2*)&sA[0][aR1][aC1 >> 1] = pa1;
        } else {
            *(uint2*)&sA[0][aR0][aC0 >> 1] = ah0;
            *(uint2*)&sA[0][aR1][aC1 >> 1] = ah1;
        }
        uint4 pb = make_uint4(pack_h2(bv0.x, bv1.x), pack_h2(bv0.y, bv1.y),
                              pack_h2(bv0.z, bv1.z), pack_h2(bv0.w, bv1.w));
        *(uint4*)&sB[0][kp][bn4] = pb;
    }
    __syncthreads();

    float acc[4][4][4] = {};
    int buf = 0;

    for (int kt = 0; kt < KT; ++kt) {
        // prefetch next k-slab
        if (kt + 1 < KT) {
            int k16 = (kt + 1) * BK;
            if (PHASE1) {
                av0 = *(const float4*)(Ain + aOfs0 + k16);
                av1 = *(const float4*)(Ain + aOfs1 + k16);
            } else {
                ah0 = *(const uint2*)(g_h + aOfs0 + k16);
                ah1 = *(const uint2*)(g_h + aOfs1 + k16);
            }
            bv0 = *(const float4*)(W + bOfs + (size_t)k16 * NDIM);
            bv1 = *(const float4*)(W + bOfs + (size_t)k16 * NDIM + NDIM);
        }

        // fragments + 16 HMMA (one k16 slice per stage)
        unsigned A0[4], A1[4], A2[4], A3[4];
#pragma unroll
        for (int mt = 0; mt < 4; mt++) {
            int row = wr * 64 + mt * 16;
            A0[mt] = *(const unsigned*)&sA[buf][row + gid    ][t4    ];
            A1[mt] = *(const unsigned*)&sA[buf][row + gid + 8][t4    ];
            A2[mt] = *(const unsigned*)&sA[buf][row + gid    ][t4 + 4];
            A3[mt] = *(const unsigned*)&sA[buf][row + gid + 8][t4 + 4];
        }
        unsigned B0[4], B1[4];
#pragma unroll
        for (int nt = 0; nt < 4; nt++) {
            int col = wc * 32 + nt * 8 + gid;
            B0[nt] = *(const unsigned*)&sB[buf][t4    ][col];
            B1[nt] = *(const unsigned*)&sB[buf][t4 + 4][col];
        }
#pragma unroll
        for (int mt = 0; mt < 4; mt++)
#pragma unroll
            for (int nt = 0; nt < 4; nt++)
                MMA_F16(acc[mt][nt], A0[mt], A1[mt], A2[mt], A3[mt], B0[nt], B1[nt]);

        // store next stage
        if (kt + 1 < KT) {
            int nb = buf ^ 1;
            if (PHASE1) {
                uint2 pa0 = make_uint2(pack_h2(av0.x, av0.y), pack_h2(av0.z, av0.w));
                uint2 pa1 = make_uint2(pack_h2(av1.x, av1.y), pack_h2(av1.z, av1.w));
                *(uint2*)&sA[nb][aR0][aC0 >> 1] = pa0;
                *(uint2*)&sA[nb][aR1][aC1 >> 1] = pa1;
            } else {
                *(uint2*)&sA[nb][aR0][aC0 >> 1] = ah0;
                *(uint2*)&sA[nb][aR1][aC1 >> 1] = ah1;
            }
            uint4 pb = make_uint4(pack_h2(bv0.x, bv1.x), pack_h2(bv0.y, bv1.y),
                                  pack_h2(bv0.z, bv1.z), pack_h2(bv0.w, bv1.w));
            *(uint4*)&sB[nb][kp][bn4] = pb;
        }
        __syncthreads();
        buf ^= 1;
    }

    // ---- epilogue ----
#pragma unroll
    for (int nt = 0; nt < 4; nt++) {
        int colg = n0 + wc * 32 + nt * 8 + t4 * 2;
        float bv0e = 0.0f, bv1e = 0.0f;
        if (PHASE1) {
            bv0e = __ldg(biasBase + (size_t)e * HDIM + colg);
            bv1e = __ldg(biasBase + (size_t)e * HDIM + colg + 1);
        }
#pragma unroll
        for (int mt = 0; mt < 4; mt++) {
            int r0e = m0 + wr * 64 + mt * 16 + gid;
            int r1e = r0e + 8;
            if (PHASE1) {
                if (r0e < cnt) {
                    float h0 = gelu_fast(acc[mt][nt][0] + bv0e);
                    float h1 = gelu_fast(acc[mt][nt][1] + bv1e);
                    *(__half2*)(g_h + (size_t)(off + r0e) * HDIM + colg) =
                        __floats2half2_rn(h0, h1);
                }
                if (r1e < cnt) {
                    float h0 = gelu_fast(acc[mt][nt][2] + bv0e);
                    float h1 = gelu_fast(acc[mt][nt][3] + bv1e);
                    *(__half2*)(g_h + (size_t)(off + r1e) * HDIM + colg) =
                        __floats2half2_rn(h0, h1);
                }
            } else {
                if (r0e < cnt) {
                    float2 v = make_float2(acc[mt][nt][0], acc[mt][nt][1]);
                    *(float2*)(g_y + (size_t)(off + r0e) * DDIM + colg) = v;
                }
                if (r1e < cnt) {
                    float2 v = make_float2(acc[mt][nt][2], acc[mt][nt][3]);
                    *(float2*)(g_y + (size_t)(off + r1e) * DDIM + colg) = v;
                }
            }
        }
    }
}

// ------------------------- combine (verbatim from R3) ----------------------
__global__ __launch_bounds__(256) void combine_kernel(
    const float* __restrict__ b2, float* __restrict__ out)
{
    int tok = blockIdx.x;
    int e0 = g_tok_e[2 * tok], e1 = g_tok_e[2 * tok + 1];
    float gg0 = g_tok_g[2 * tok], gg1 = g_tok_g[2 * tok + 1];
    int p0 = g_tok_pos[2 * tok], p1 = g_tok_pos[2 * tok + 1];
    int j = threadIdx.x * 4;
    float4 y0 = *(const float4*)(g_y + (size_t)p0 * DDIM + j);
    float4 y1 = *(const float4*)(g_y + (size_t)p1 * DDIM + j);
    float4 b0 = *(const float4*)(b2 + (size_t)e0 * DDIM + j);
    float4 b1v = *(const float4*)(b2 + (size_t)e1 * DDIM + j);
    float4 o;
    o.x = gg0 * (y0.x + b0.x) + gg1 * (y1.x + b1v.x);
    o.y = gg0 * (y0.y + b0.y) + gg1 * (y1.y + b1v.y);
    o.z = gg0 * (y0.z + b0.z) + gg1 * (y1.z + b1v.z);
    o.w = gg0 * (y0.w + b0.w) + gg1 * (y1.w + b1v.w);
    *(float4*)(out + (size_t)tok * DDIM + j) = o;
}

// ------------------------- launch ------------------------------------------
extern "C" void kernel_launch(void* const* d_in, const int* in_sizes, int n_in,
                              void* d_out, int out_size) {
    const float* x  = (const float*)d_in[0];
    const float* rw = (const float*)d_in[1];
    const float* rb = (const float*)d_in[2];
    const float* w1 = (const float*)d_in[3];
    const float* b1 = (const float*)d_in[4];
    const float* w2 = (const float*)d_in[5];
    const float* b2 = (const float*)d_in[6];
    float* out = (float*)d_out;

    init_kernel<<<1, 32>>>();
    router_kernel<<<NTOK / 8, 256>>>(x, rw, rb);
    scan_kernel<<<1, 32>>>();
    build_kernel<<<(NTOK + 255) / 256, 256>>>();

    // GEMM1: [cnt,1024] @ [1024,4096] -> gelu -> g_h (fp16)
    gemm_hmma<DDIM, true ><<<dim3(HDIM / BN, NASSIGN / BM, NEXP), 256>>>(x, w1, b1);
    // GEMM2: [cnt,4096] @ [4096,1024] -> g_y (fp32)
    gemm_hmma<HDIM, false><<<dim3(DDIM / BN, NASSIGN / BM, NEXP), 256>>>(x, w2, b1);

    combine_kernel<<<NTOK, 256>>>(b2, out);
}